// round 14
// baseline (speedup 1.0000x reference)
#include <cuda_runtime.h>
#include <cuda_fp16.h>

// Problem constants
#define PW 32
#define PL 64
#define PK 512
#define PN 64
#define ROWS_PER_W (PL * PK)            // 32768
#define TOTAL_ROWS (PW * ROWS_PER_W)    // 1048576
#define EN_ELEMS   TOTAL_ROWS

// Scratch (no allocs allowed -> __device__ global)
__device__ unsigned long long  g_packed[TOTAL_ROWS];   // 8 MB: states rows as 64-bit masks

#define QT_STRIDE 72  // halves; padded -> conflict-free column reads

// lo-split scaling: keeps all lo-split values in fp16 normal range
#define LO_SCALE      2048.0f
#define LO_SCALE_INV  4.8828125e-4f   // 2^-11

__device__ __forceinline__ unsigned pack_f16(float lo, float hi) {
    __half2 h = __floats2half2_rn(lo, hi);  // x=lo (low 16 bits), y=hi
    return *reinterpret_cast<unsigned*>(&h);
}

__device__ __forceinline__ void mma_f16(float* d, const unsigned* a, unsigned b0, unsigned b1) {
    asm volatile(
        "mma.sync.aligned.m16n8k16.row.col.f32.f16.f16.f32 "
        "{%0,%1,%2,%3}, {%4,%5,%6,%7}, {%8,%9}, {%0,%1,%2,%3};"
        : "+f"(d[0]), "+f"(d[1]), "+f"(d[2]), "+f"(d[3])
        : "r"(a[0]), "r"(a[1]), "r"(a[2]), "r"(a[3]), "r"(b0), "r"(b1));
}

// ---------------------------------------------------------------------------
// Kernel 1: energies via SCALED fp16-split MMA (R6/R9-proven structure).
//   Q = hi + lo*2^-11, both fp16 with all values in the NORMAL range:
//   hi = fp16(q) (11 mantissa bits), lo = fp16((q-hi)*2^11) (11 more bits,
//   scaled out of the subnormal zone that made R12's unscaled lo slow).
//   s in {0,1} exact in fp16 -> fp32-equivalent energies (~2e-7 rel).
//   Two passes (hi, then lo folded with weight 2^-11) over the nt-outer
//   fold-early loop; warp owns 64 rows (4 blocks of 16), B fragments loaded
//   once per (pass,nt) and shared across blocks. vs R9: -33% MMAs and LDS.
// ---------------------------------------------------------------------------
__global__ void __launch_bounds__(256, 2)
energies_kernel(const float* __restrict__ states,
                const float* __restrict__ Qg,
                float* __restrict__ energies_out) {
    const int w   = blockIdx.y;    // 0..31
    const int cta = blockIdx.x;    // 0..63
    const int tid = threadIdx.x;

    __shared__ __half sQT[2][PN * QT_STRIDE];

    // Build Q^T fp16 splits in smem: hi + scaled lo
    const float* Qw = Qg + (size_t)w * PN * PN;
    for (int idx = tid; idx < PN * PN; idx += 256) {
        const int i = idx >> 6;
        const int j = idx & 63;
        float q = Qw[idx];
        __half h = __float2half_rn(q);
        float r = (q - __half2float(h)) * LO_SCALE;
        __half lo = __float2half_rn(r);
        sQT[0][j * QT_STRIDE + i] = h;
        sQT[1][j * QT_STRIDE + i] = lo;
    }
    __syncthreads();

    const int warp = tid >> 5;
    const int lane = tid & 31;
    const int g  = lane >> 2;  // 0..7
    const int tg = lane & 3;   // 0..3

    const int row_base = w * ROWS_PER_W + cta * 512 + warp * 64;

    // A fragments for 4 blocks of 16 rows (64 regs), loaded upfront (high MLP).
    // __ldcs: states are read exactly once -> streaming, keep L2 clean.
    unsigned af[4][4][4];
    #pragma unroll
    for (int bi = 0; bi < 4; bi++) {
        const float* rowg  = states + (size_t)(row_base + bi * 16 + g) * PN;
        const float* rowg8 = rowg + 8 * PN;
        #pragma unroll
        for (int kc = 0; kc < 4; kc++) {
            const int c0 = kc * 16 + tg * 2;
            float2 v;
            v = __ldcs(reinterpret_cast<const float2*>(rowg  + c0));     af[bi][kc][0] = pack_f16(v.x, v.y);
            v = __ldcs(reinterpret_cast<const float2*>(rowg8 + c0));     af[bi][kc][1] = pack_f16(v.x, v.y);
            v = __ldcs(reinterpret_cast<const float2*>(rowg  + c0 + 8)); af[bi][kc][2] = pack_f16(v.x, v.y);
            v = __ldcs(reinterpret_cast<const float2*>(rowg8 + c0 + 8)); af[bi][kc][3] = pack_f16(v.x, v.y);
        }
    }

    float eg[4]  = {0.f, 0.f, 0.f, 0.f};
    float eg8[4] = {0.f, 0.f, 0.f, 0.f};

    // Two passes: sp=0 (hi, weight 1) then sp=1 (lo, weight 2^-11).
    #pragma unroll
    for (int sp = 0; sp < 2; sp++) {
        const float scale = sp ? LO_SCALE_INV : 1.0f;
        #pragma unroll
        for (int nt = 0; nt < 8; nt++) {
            const int kc0 = nt >> 1;
            const int rlo = (nt & 1) ? 2 : 0;
            const int rhi = (nt & 1) ? 3 : 1;

            float d[4][4];
            #pragma unroll
            for (int bi = 0; bi < 4; bi++)
                #pragma unroll
                for (int e = 0; e < 4; e++) d[bi][e] = 0.0f;

            const int n = nt * 8 + g;
            const __half* qt = sQT[sp] + n * QT_STRIDE + tg * 2;
            unsigned b0[4], b1[4];
            #pragma unroll
            for (int kc = 0; kc < 4; kc++) {
                b0[kc] = *reinterpret_cast<const unsigned*>(qt + kc * 16);
                b1[kc] = *reinterpret_cast<const unsigned*>(qt + kc * 16 + 8);
            }
            #pragma unroll
            for (int kc = 0; kc < 4; kc++)
                #pragma unroll
                for (int bi = 0; bi < 4; bi++)
                    mma_f16(d[bi], af[bi][kc], b0[kc], b1[kc]);

            // Fold this pass's contribution (predicated FFMA with weight).
            #pragma unroll
            for (int bi = 0; bi < 4; bi++) {
                unsigned a = af[bi][kc0][rlo];
                if (a & 0xFFFFu) eg[bi]  += d[bi][0] * scale;
                if (a >> 16)     eg[bi]  += d[bi][1] * scale;
                a = af[bi][kc0][rhi];
                if (a & 0xFFFFu) eg8[bi] += d[bi][2] * scale;
                if (a >> 16)     eg8[bi] += d[bi][3] * scale;
            }
        }
    }

    // Epilogue: reduce over tg, pack state bits, store.
    // fp16(1.0) = 0x3C00 -> bit 10 (low half) / bit 26 (high half) test the s bit
    #pragma unroll
    for (int bi = 0; bi < 4; bi++) {
        float e0 = eg[bi], e8 = eg8[bi];
        e0 += __shfl_xor_sync(0xffffffffu, e0, 1);
        e0 += __shfl_xor_sync(0xffffffffu, e0, 2);
        e8 += __shfl_xor_sync(0xffffffffu, e8, 1);
        e8 += __shfl_xor_sync(0xffffffffu, e8, 2);

        unsigned plo = 0, phi = 0, qlo = 0, qhi = 0;
        #pragma unroll
        for (int kc = 0; kc < 4; kc++) {
            const unsigned a0 = af[bi][kc][0], a1 = af[bi][kc][1];
            const unsigned a2 = af[bi][kc][2], a3 = af[bi][kc][3];
            unsigned m0 = ((a0 >> 10) & 1u) | ((a0 >> 25) & 2u)
                        | (((a2 >> 10) & 1u) << 8) | (((a2 >> 25) & 2u) << 8);
            unsigned m8 = ((a1 >> 10) & 1u) | ((a1 >> 25) & 2u)
                        | (((a3 >> 10) & 1u) << 8) | (((a3 >> 25) & 2u) << 8);
            const int sh = (kc & 1) * 16 + tg * 2;
            if (kc < 2) { plo |= m0 << sh; qlo |= m8 << sh; }
            else        { phi |= m0 << sh; qhi |= m8 << sh; }
        }
        plo |= __shfl_xor_sync(0xffffffffu, plo, 1);
        plo |= __shfl_xor_sync(0xffffffffu, plo, 2);
        phi |= __shfl_xor_sync(0xffffffffu, phi, 1);
        phi |= __shfl_xor_sync(0xffffffffu, phi, 2);
        qlo |= __shfl_xor_sync(0xffffffffu, qlo, 1);
        qlo |= __shfl_xor_sync(0xffffffffu, qlo, 2);
        qhi |= __shfl_xor_sync(0xffffffffu, qhi, 1);
        qhi |= __shfl_xor_sync(0xffffffffu, qhi, 2);

        if (tg == 0) {
            const int r0 = row_base + bi * 16 + g;
            energies_out[r0]     = e0;
            energies_out[r0 + 8] = e8;
            reinterpret_cast<uint2*>(g_packed)[r0]     = make_uint2(plo, phi);
            reinterpret_cast<uint2*>(g_packed)[r0 + 8] = make_uint2(qlo, qhi);
        }
    }
}

// ---------------------------------------------------------------------------
// Kernel 2: fused mask + row-gather swap, LANE-COALESCED stores.
//   (Byte-identical to R9's proven 48.6us kernel.)
// ---------------------------------------------------------------------------
__global__ void __launch_bounds__(256)
swap_kernel(const float* __restrict__ energies,
            const float* __restrict__ beta,
            const float* __restrict__ u,
            float* __restrict__ out_states) {
    const int gwarp = (blockIdx.x * 256 + threadIdx.x) >> 5;  // 0 .. TOTAL_ROWS/8-1
    const int lane  = threadIdx.x & 31;
    const int row0  = gwarp << 3;

    const int r = row0 + (lane & 7);
    const int k = r & 511;
    const int l = (r >> 9) & 63;
    const int w = r >> 15;
    const int j = (l == 0) ? 0 : (l - 1);
    const float e1 = energies[(w * PL + j) * PK + k];
    const float e2 = energies[(w * PL + j + 1) * PK + k];
    const float db = beta[j + 1] - beta[j];
    const bool  m  = u[(w * 63 + j) * PK + k] < expf((e2 - e1) * db);
    int src;
    if (l == 0) src = m ? 1 : 0;
    else        src = m ? (l - 1) : l;
    const int my_src_row = (w * PL + src) * PK + k;

    const uint2* packed = reinterpret_cast<const uint2*>(g_packed);
    float4* out4 = reinterpret_cast<float4*>(out_states) + ((size_t)row0 << 4);

    #pragma unroll
    for (int qq = 0; qq < 4; qq++) {
        const int c   = qq * 32 + lane;   // float4 chunk 0..127 within warp block
        const int rib = c >> 4;           // row-in-block 0..7
        const int sub = c & 15;           // float4 index within row
        const int src_row = __shfl_sync(0xffffffffu, my_src_row, rib);
        const uint2 pk = packed[src_row];
        const unsigned word = (sub & 8) ? pk.y : pk.x;
        const unsigned nib  = (word >> ((sub & 7) * 4)) & 0xFu;
        float4 v;
        v.x = (nib & 1u) ? 1.0f : 0.0f;
        v.y = (nib & 2u) ? 1.0f : 0.0f;
        v.z = (nib & 4u) ? 1.0f : 0.0f;
        v.w = (nib & 8u) ? 1.0f : 0.0f;
        __stcs(out4 + c, v);   // streaming store: output never re-read
    }
}

// ---------------------------------------------------------------------------

extern "C" void kernel_launch(void* const* d_in, const int* in_sizes, int n_in,
                              void* d_out, int out_size) {
    const float* states = (const float*)d_in[0];  // (32,64,512,64) f32
    const float* Q      = (const float*)d_in[1];  // (32,64,64) f32
    const float* beta   = (const float*)d_in[2];  // (64,) f32
    const float* u      = (const float*)d_in[3];  // (32,63,512) f32

    float* energies   = (float*)d_out;
    float* out_states = (float*)d_out + EN_ELEMS;

    dim3 egrid(64, PW);
    energies_kernel<<<egrid, 256>>>(states, Q, energies);

    swap_kernel<<<(TOTAL_ROWS * 4) / 256, 256>>>(energies, beta, u, out_states);
}

// round 15
// speedup vs baseline: 1.2946x; 1.2946x over previous
#include <cuda_runtime.h>
#include <cuda_bf16.h>

// Problem constants
#define PW 32
#define PL 64
#define PK 512
#define PN 64
#define ROWS_PER_W (PL * PK)            // 32768
#define TOTAL_ROWS (PW * ROWS_PER_W)    // 1048576
#define EN_ELEMS   TOTAL_ROWS

// Scratch (no allocs allowed -> __device__ global)
__device__ unsigned long long  g_packed[TOTAL_ROWS];   // 8 MB: states rows as 64-bit masks

#define QT_STRIDE 72  // halves; padded -> conflict-free column reads

__device__ __forceinline__ void mma_bf16(float* d, const unsigned* a, unsigned b0, unsigned b1) {
    asm volatile(
        "mma.sync.aligned.m16n8k16.row.col.f32.bf16.bf16.f32 "
        "{%0,%1,%2,%3}, {%4,%5,%6,%7}, {%8,%9}, {%0,%1,%2,%3};"
        : "+f"(d[0]), "+f"(d[1]), "+f"(d[2]), "+f"(d[3])
        : "r"(a[0]), "r"(a[1]), "r"(a[2]), "r"(a[3]), "r"(b0), "r"(b1));
}

// states are EXACTLY 0.0f or 1.0f -> bf16 = high halfword. One PRMT packs two.
__device__ __forceinline__ unsigned pack01(uint2 v) {
    return __byte_perm(v.x, v.y, 0x7632);
}

// ---------------------------------------------------------------------------
// Kernel 1: energies via bf16-split MMA — phase-desynchronized build.
//   Math identical to R6/R9 (3x bf16 split, ~24 mantissa bits, rel ~2.8e-7).
//   Changes vs R9 (which ran load-phase then MMA-phase serially):
//     * 128-thread CTAs at 4/SM: RF exactly fits, 4 independently rotating
//       CTA slots desynchronize load/MMA phases so DRAM and tensor overlap.
//     * pair-split nt-loops: first MMAs depend only on blocks {0,1}; the
//       LDGs of blocks {2,3} complete under the pair-0 MMA shadow.
//     * PRMT-based exact packing (states in {0,1}) shortens load->use chains.
// ---------------------------------------------------------------------------
__global__ void __launch_bounds__(128, 4)
energies_kernel(const float* __restrict__ states,
                const float* __restrict__ Qg,
                float* __restrict__ energies_out) {
    const int w   = blockIdx.y;    // 0..31
    const int cta = blockIdx.x;    // 0..127
    const int tid = threadIdx.x;   // 0..127

    __shared__ __nv_bfloat16 sQT[3][PN * QT_STRIDE];   // 27.6 KB

    // Build Q^T splits in smem (Q = hi + mid + lo, ~24 mantissa bits)
    const float* Qw = Qg + (size_t)w * PN * PN;
    for (int idx = tid; idx < PN * PN; idx += 128) {
        const int i = idx >> 6;
        const int j = idx & 63;
        float q = Qw[idx];
        __nv_bfloat16 h = __float2bfloat16(q);
        float r = q - __bfloat162float(h);
        __nv_bfloat16 m = __float2bfloat16(r);
        float r2 = r - __bfloat162float(m);
        __nv_bfloat16 lo = __float2bfloat16(r2);
        sQT[0][j * QT_STRIDE + i] = h;
        sQT[1][j * QT_STRIDE + i] = m;
        sQT[2][j * QT_STRIDE + i] = lo;
    }
    __syncthreads();

    const int warp = tid >> 5;   // 0..3
    const int lane = tid & 31;
    const int g  = lane >> 2;    // 0..7
    const int tg = lane & 3;     // 0..3

    const int row_base = w * ROWS_PER_W + cta * 256 + warp * 64;

    // A fragments for 4 blocks of 16 rows. All LDGs issue here (high MLP);
    // the pair-0 MMA loop below waits only on blocks {0,1}.
    unsigned af[4][4][4];
    #pragma unroll
    for (int bi = 0; bi < 4; bi++) {
        const float* rowg  = states + (size_t)(row_base + bi * 16 + g) * PN;
        const float* rowg8 = rowg + 8 * PN;
        #pragma unroll
        for (int kc = 0; kc < 4; kc++) {
            const int c0 = kc * 16 + tg * 2;
            af[bi][kc][0] = pack01(*reinterpret_cast<const uint2*>(rowg  + c0));
            af[bi][kc][1] = pack01(*reinterpret_cast<const uint2*>(rowg8 + c0));
            af[bi][kc][2] = pack01(*reinterpret_cast<const uint2*>(rowg  + c0 + 8));
            af[bi][kc][3] = pack01(*reinterpret_cast<const uint2*>(rowg8 + c0 + 8));
        }
    }

    // Process pairs of blocks: {0,1} then {2,3}.
    #pragma unroll
    for (int p = 0; p < 2; p++) {
        const int b0i = 2 * p;
        float eg[2]  = {0.f, 0.f};
        float eg8[2] = {0.f, 0.f};

        // bf16(1.0) = 0x3F80 -> bit 7 (lo half) / bit 23 (hi half) = the s bit
        #pragma unroll
        for (int nt = 0; nt < 8; nt++) {
            const int kc0 = nt >> 1;
            const int rlo = (nt & 1) ? 2 : 0;
            const int rhi = (nt & 1) ? 3 : 1;

            float d[2][4];
            #pragma unroll
            for (int bi = 0; bi < 2; bi++)
                #pragma unroll
                for (int e = 0; e < 4; e++) d[bi][e] = 0.0f;

            const int n = nt * 8 + g;
            #pragma unroll
            for (int sp = 0; sp < 3; sp++) {
                const __nv_bfloat16* qt = sQT[sp] + n * QT_STRIDE + tg * 2;
                unsigned b0[4], b1[4];
                #pragma unroll
                for (int kc = 0; kc < 4; kc++) {
                    b0[kc] = *reinterpret_cast<const unsigned*>(qt + kc * 16);
                    b1[kc] = *reinterpret_cast<const unsigned*>(qt + kc * 16 + 8);
                }
                #pragma unroll
                for (int kc = 0; kc < 4; kc++) {
                    mma_bf16(d[0], af[b0i][kc],     b0[kc], b1[kc]);
                    mma_bf16(d[1], af[b0i + 1][kc], b0[kc], b1[kc]);
                }
            }

            // Fold this nt's 8 j-columns into the scalar energies.
            #pragma unroll
            for (int bi = 0; bi < 2; bi++) {
                unsigned a = af[b0i + bi][kc0][rlo];
                if (a & 0x80u)     eg[bi]  += d[bi][0];
                if (a & 0x800000u) eg[bi]  += d[bi][1];
                a = af[b0i + bi][kc0][rhi];
                if (a & 0x80u)     eg8[bi] += d[bi][2];
                if (a & 0x800000u) eg8[bi] += d[bi][3];
            }
        }

        // Epilogue for this pair: reduce over tg, pack state bits, store.
        #pragma unroll
        for (int bi = 0; bi < 2; bi++) {
            const int gb = b0i + bi;
            float e0 = eg[bi], e8 = eg8[bi];
            e0 += __shfl_xor_sync(0xffffffffu, e0, 1);
            e0 += __shfl_xor_sync(0xffffffffu, e0, 2);
            e8 += __shfl_xor_sync(0xffffffffu, e8, 1);
            e8 += __shfl_xor_sync(0xffffffffu, e8, 2);

            unsigned plo = 0, phi = 0, qlo = 0, qhi = 0;
            #pragma unroll
            for (int kc = 0; kc < 4; kc++) {
                const unsigned a0 = af[gb][kc][0], a1 = af[gb][kc][1];
                const unsigned a2 = af[gb][kc][2], a3 = af[gb][kc][3];
                unsigned m0 = ((a0 >> 7) & 1u) | ((a0 >> 22) & 2u)
                            | (((a2 >> 7) & 1u) << 8) | (((a2 >> 22) & 2u) << 8);
                unsigned m8 = ((a1 >> 7) & 1u) | ((a1 >> 22) & 2u)
                            | (((a3 >> 7) & 1u) << 8) | (((a3 >> 22) & 2u) << 8);
                const int sh = (kc & 1) * 16 + tg * 2;
                if (kc < 2) { plo |= m0 << sh; qlo |= m8 << sh; }
                else        { phi |= m0 << sh; qhi |= m8 << sh; }
            }
            plo |= __shfl_xor_sync(0xffffffffu, plo, 1);
            plo |= __shfl_xor_sync(0xffffffffu, plo, 2);
            phi |= __shfl_xor_sync(0xffffffffu, phi, 1);
            phi |= __shfl_xor_sync(0xffffffffu, phi, 2);
            qlo |= __shfl_xor_sync(0xffffffffu, qlo, 1);
            qlo |= __shfl_xor_sync(0xffffffffu, qlo, 2);
            qhi |= __shfl_xor_sync(0xffffffffu, qhi, 1);
            qhi |= __shfl_xor_sync(0xffffffffu, qhi, 2);

            if (tg == 0) {
                const int r0 = row_base + gb * 16 + g;
                energies_out[r0]     = e0;
                energies_out[r0 + 8] = e8;
                reinterpret_cast<uint2*>(g_packed)[r0]     = make_uint2(plo, phi);
                reinterpret_cast<uint2*>(g_packed)[r0 + 8] = make_uint2(qlo, qhi);
            }
        }
    }
}

// ---------------------------------------------------------------------------
// Kernel 2: fused mask + row-gather swap, LANE-COALESCED stores.
//   (Byte-identical to R9's proven 48.6us kernel.)
// ---------------------------------------------------------------------------
__global__ void __launch_bounds__(256)
swap_kernel(const float* __restrict__ energies,
            const float* __restrict__ beta,
            const float* __restrict__ u,
            float* __restrict__ out_states) {
    const int gwarp = (blockIdx.x * 256 + threadIdx.x) >> 5;  // 0 .. TOTAL_ROWS/8-1
    const int lane  = threadIdx.x & 31;
    const int row0  = gwarp << 3;

    const int r = row0 + (lane & 7);
    const int k = r & 511;
    const int l = (r >> 9) & 63;
    const int w = r >> 15;
    const int j = (l == 0) ? 0 : (l - 1);
    const float e1 = energies[(w * PL + j) * PK + k];
    const float e2 = energies[(w * PL + j + 1) * PK + k];
    const float db = beta[j + 1] - beta[j];
    const bool  m  = u[(w * 63 + j) * PK + k] < expf((e2 - e1) * db);
    int src;
    if (l == 0) src = m ? 1 : 0;
    else        src = m ? (l - 1) : l;
    const int my_src_row = (w * PL + src) * PK + k;

    const uint2* packed = reinterpret_cast<const uint2*>(g_packed);
    float4* out4 = reinterpret_cast<float4*>(out_states) + ((size_t)row0 << 4);

    #pragma unroll
    for (int qq = 0; qq < 4; qq++) {
        const int c   = qq * 32 + lane;   // float4 chunk 0..127 within warp block
        const int rib = c >> 4;           // row-in-block 0..7
        const int sub = c & 15;           // float4 index within row
        const int src_row = __shfl_sync(0xffffffffu, my_src_row, rib);
        const uint2 pk = packed[src_row];
        const unsigned word = (sub & 8) ? pk.y : pk.x;
        const unsigned nib  = (word >> ((sub & 7) * 4)) & 0xFu;
        float4 v;
        v.x = (nib & 1u) ? 1.0f : 0.0f;
        v.y = (nib & 2u) ? 1.0f : 0.0f;
        v.z = (nib & 4u) ? 1.0f : 0.0f;
        v.w = (nib & 8u) ? 1.0f : 0.0f;
        __stcs(out4 + c, v);   // streaming store: output never re-read
    }
}

// ---------------------------------------------------------------------------

extern "C" void kernel_launch(void* const* d_in, const int* in_sizes, int n_in,
                              void* d_out, int out_size) {
    const float* states = (const float*)d_in[0];  // (32,64,512,64) f32
    const float* Q      = (const float*)d_in[1];  // (32,64,64) f32
    const float* beta   = (const float*)d_in[2];  // (64,) f32
    const float* u      = (const float*)d_in[3];  // (32,63,512) f32

    float* energies   = (float*)d_out;
    float* out_states = (float*)d_out + EN_ELEMS;

    dim3 egrid(128, PW);
    energies_kernel<<<egrid, 128>>>(states, Q, energies);

    swap_kernel<<<(TOTAL_ROWS * 4) / 256, 256>>>(energies, beta, u, out_states);
}